// round 10
// baseline (speedup 1.0000x reference)
#include <cuda_runtime.h>

#define NN 8192
#define NE 16384
#define NCTA 128          // each CTA owns 128 columns
#define TPB 1024
#define NCH 16            // chunks per CTA, 8 cols (2 quads) each
#define NIT 16            // 8192 rows / 512 row-groups

// smem: su[8192] | sv[8192] | sout[8192] | swA[32][2]f4 | swB[32][2]f4 | seai[2]f4 | seao[2]f4
#define SMEM_BYTES ((3 * NN) * 4 + 32 * 2 * 16 * 2 + 4 * 16)

// ---- scratch (device globals; no allocation allowed) ----
__device__ float g_u[NN];
__device__ float g_v[NN];
__device__ float g_c[NN];
__device__ float g_outp[NCTA][NN];
__device__ int   g_flag[NCH + 1][NCTA];

__device__ __forceinline__ int ld_acq(const int* p) {
    int v;
    asm volatile("ld.acquire.gpu.s32 %0, [%1];" : "=r"(v) : "l"(p) : "memory");
    return v;
}
__device__ __forceinline__ void st_rel(int* p, int v) {
    asm volatile("st.release.gpu.s32 [%0], %1;" :: "l"(p), "r"(v) : "memory");
}
__device__ __forceinline__ void f4add(float4& a, const float4 b) {
    a.x += b.x; a.y += b.y; a.z += b.z; a.w += b.w;
}
__device__ __forceinline__ void f4fma(float4& a, const float4 b, float s) {
    a.x += b.x * s; a.y += b.y * s; a.z += b.z * s; a.w += b.w * s;
}
__device__ __forceinline__ float dot4(const float4 a, const float4 b) {
    return a.x * b.x + a.y * b.y + a.z * b.z + a.w * b.w;
}
__device__ __forceinline__ float4 ldcg4(const float* p) {   // DRAM stream, keep in L2
    float4 r;
    asm volatile("ld.global.cg.v4.f32 {%0,%1,%2,%3}, [%4];"
                 : "=f"(r.x), "=f"(r.y), "=f"(r.z), "=f"(r.w) : "l"(p));
    return r;
}
__device__ __forceinline__ float4 ldcs4(const float* p) {   // evict-first (last touch)
    float4 r;
    asm volatile("ld.global.cs.v4.f32 {%0,%1,%2,%3}, [%4];"
                 : "=f"(r.x), "=f"(r.y), "=f"(r.z), "=f"(r.w) : "l"(p));
    return r;
}
__device__ __forceinline__ void bfly4(float4& a, int off) {
    a.x += __shfl_xor_sync(0xffffffffu, a.x, off);
    a.y += __shfl_xor_sync(0xffffffffu, a.y, off);
    a.z += __shfl_xor_sync(0xffffffffu, a.z, off);
    a.w += __shfl_xor_sync(0xffffffffu, a.w, off);
}

__global__ void k1_prep(const float* __restrict__ X, const float* __restrict__ kw) {
    int n = blockIdx.x * blockDim.x + threadIdx.x;
    int* fl = &g_flag[0][0];
    for (int i = n; i < (NCH + 1) * NCTA; i += NN) fl[i] = 0;
    if (n >= NN) return;
    float4 x = reinterpret_cast<const float4*>(X)[n];
    g_u[n] = x.x * kw[0] + x.y * kw[1] + x.z * kw[2]  + x.w * kw[3];
    g_v[n] = x.x * kw[4] + x.y * kw[5] + x.z * kw[6]  + x.w * kw[7];
    g_c[n] = x.x * kw[8] + x.y * kw[9] + x.z * kw[10] + x.w * kw[11];
}

__global__ __launch_bounds__(TPB, 1) void big(const float* __restrict__ Ri,
                                              const float* __restrict__ Ro,
                                              const float* __restrict__ ew) {
    extern __shared__ float smem[];
    float*  su   = smem;
    float*  sv   = smem + NN;
    float*  sout = smem + 2 * NN;
    float4* swA  = reinterpret_cast<float4*>(smem + 3 * NN);   // [32][2]
    float4* swB  = swA + 64;                                   // [32][2]
    float4* seai = swB + 64;                                   // [2]
    float4* seao = seai + 2;                                   // [2]

    const int t   = threadIdx.x;
    const int cta = blockIdx.x;
    const int g   = t >> 1;          // row group 0..511
    const int ql  = t & 1;           // quad within 8-col chunk
    const int l32 = t & 31;
    const int w   = t >> 5;

    for (int i = t; i < NN; i += TPB) { su[i] = g_u[i]; sv[i] = g_v[i]; sout[i] = 0.f; }
    __syncthreads();

    const int qbase = cta * 32;      // global quad base for this CTA

    for (int s = 0; s <= NCH; ++s) {
        // pacing gate: bound drift to <=1 phase (steady state: passes instantly)
        if (s >= 2) {
            if (t < 32) {
                const int* fl = g_flag[s - 1];
                for (;;) {
                    bool ok = true;
                    for (int i = l32; i < NCTA; i += 32) ok &= (ld_acq(&fl[i]) != 0);
                    if (__all_sync(0xffffffffu, ok)) break;
                    __nanosleep(64);
                }
            }
            __syncthreads();
        }
        const bool P1 = (s < NCH);
        const bool P2 = (s >= 1);
        float4 eai = make_float4(0.f, 0.f, 0.f, 0.f);
        float4 eao = make_float4(0.f, 0.f, 0.f, 0.f);
        if (P2) { eai = seai[ql]; eao = seao[ql]; }   // published end of prev phase

        const size_t cA = (size_t)(qbase + s * 2 + ql) * 4;   // float offset, chunk s
        const size_t cB = cA - 8;                             // chunk s-1, same quad slot
        float4 pai = make_float4(0.f, 0.f, 0.f, 0.f);
        float4 pao = make_float4(0.f, 0.f, 0.f, 0.f);

#pragma unroll 4
        for (int i = 0; i < NIT; ++i) {
            const int n = i * 512 + g;
            const size_t ro = (size_t)n * NE;
            if (P1) {   // DRAM leg: col-reduce partials for chunk s
                const float4 a = ldcg4(Ri + ro + cA);
                const float4 b = ldcg4(Ro + ro + cA);
                f4fma(pai, b, su[n]);     // ai += Ro * u
                f4fma(pao, a, sv[n]);     // ao += Ri * v
            }
            if (P2) {   // L2 leg: row-dot chunk s-1
                const float4 a = ldcs4(Ri + ro + cB);
                const float4 b = ldcs4(Ro + ro + cB);
                float dot = dot4(a, eai) + dot4(b, eao);
                dot += __shfl_xor_sync(0xffffffffu, dot, 1);
                if (ql == 0) sout[n] += dot;
            }
        }

        if (P1) {
            // reduce over 16 same-parity lanes (row groups) within warp
            bfly4(pai, 2); bfly4(pai, 4); bfly4(pai, 8); bfly4(pai, 16);
            bfly4(pao, 2); bfly4(pao, 4); bfly4(pao, 8); bfly4(pao, 16);
            if (l32 < 2) { swA[w * 2 + l32] = pai; swB[w * 2 + l32] = pao; }
        }
        __syncthreads();
        if (P1 && t < 32) {
            // cross-warp reduce: lane = mat(1b) | ql(1b) | seg(3b)
            const int mat = t >> 4, qll = (t >> 3) & 1, seg = t & 7;
            const float4* src = mat ? swB : swA;
            float4 sum = make_float4(0.f, 0.f, 0.f, 0.f);
#pragma unroll
            for (int j = 0; j < 4; ++j) f4add(sum, src[(seg + j * 8) * 2 + qll]);
            bfly4(sum, 1); bfly4(sum, 2); bfly4(sum, 4);
            if (seg == 0) {
                const float4 wv = reinterpret_cast<const float4*>(ew)[qbase + s * 2 + qll];
                sum.x *= wv.x; sum.y *= wv.y; sum.z *= wv.z; sum.w *= wv.w;
                if (mat) seao[qll] = sum; else seai[qll] = sum;
            }
        }
        __syncthreads();
        if (t == 0) st_rel(&g_flag[s][cta], 1);
    }

    for (int i = t; i < NN; i += TPB) g_outp[cta][i] = sout[i];
}

// out[n] = sum_p outp[p][n] + c[n]  (fixed order, deterministic)
__global__ void kfin(float* __restrict__ out) {
    const int n = blockIdx.x * blockDim.x + threadIdx.x;
    if (n >= NN) return;
    float s = g_c[n];
#pragma unroll 8
    for (int p = 0; p < NCTA; ++p) s += g_outp[p][n];
    out[n] = s;
}

extern "C" void kernel_launch(void* const* d_in, const int* in_sizes, int n_in,
                              void* d_out, int out_size) {
    const float* X    = (const float*)d_in[0];  // [N,4]
    const float* ew   = (const float*)d_in[1];  // [E,1]
    const float* Ri   = (const float*)d_in[2];  // [N,E]
    const float* Ro   = (const float*)d_in[3];  // [N,E]
    const float* kern = (const float*)d_in[4];  // [12,1]
    float* out = (float*)d_out;                 // [N,1]

    cudaFuncSetAttribute(big, cudaFuncAttributeMaxDynamicSharedMemorySize, SMEM_BYTES);
    k1_prep<<<NN / 256, 256>>>(X, kern);
    big<<<NCTA, TPB, SMEM_BYTES>>>(Ri, Ro, ew);
    kfin<<<NN / 256, 256>>>(out);
}